// round 14
// baseline (speedup 1.0000x reference)
#include <cuda_runtime.h>
#include <float.h>

#define OUT_G    32
#define NUM_SEG  32768          // 32^3
#define CAP      128            // bucket capacity (Poisson mean ~30.5; >100 essentially impossible)

// Scratch (static __device__ — no allocation allowed)
__device__ int g_counts[NUM_SEG];            // per-segment count
__device__ int g_bucket[NUM_SEG * CAP];      // fixed-capacity point-index buckets (16 MB)

// ---------------------------------------------------------------------------
// Pass 1: zero the counts. Separate kernel is mandatory:
//   - fusing the reset into pool_kernel costs +60-80us (R8 vs R9 A/B)
//   - a graph memset node costs +5us vs this kernel (R11)
// Vectorized int4 stores, 32 CTAs (ramp-overhead dominated; fewer is faster).
// ---------------------------------------------------------------------------
__global__ void zero_counts_kernel() {
    int i = blockIdx.x * blockDim.x + threadIdx.x;   // 8192 threads
    ((int4*)g_counts)[i] = make_int4(0, 0, 0, 0);    // 8192 * 16B = 128KB
}

// ---------------------------------------------------------------------------
// Pass 2: fused seg-id + scatter into fixed-capacity buckets.
// One point per thread — proven-fastest (2-pt neutral R10, 4-pt worse R3).
// ~18.5us: bound by scattered-atomic + scattered-store L1tex wavefronts.
// ---------------------------------------------------------------------------
__global__ void scatter_kernel(const int* __restrict__ coords, int n) {
    int i = blockIdx.x * blockDim.x + threadIdx.x;
    if (i >= n) return;
    int x = coords[3 * i + 0];
    int y = coords[3 * i + 1];
    int z = coords[3 * i + 2];
    int s = ((x >> 1) * OUT_G + (y >> 1)) * OUT_G + (z >> 1);
    int pos = atomicAdd(&g_counts[s], 1);
    if (pos < CAP) g_bucket[s * CAP + pos] = i;
}

// ---------------------------------------------------------------------------
// Pass 3: gather + max reduce. ONE WARP per output voxel (32 lanes x float4
// = 128 channels). Proven-optimal loop: 4 independent scalar index loads
// then 4 independent float4 gathers, branch-free body -> front-batched LDGs,
// ~5.9 TB/s (random-512B-gather ceiling). Block 256 (measured best).
// STRICTLY read-only except the final output store — no g_counts writes
// (measured toxic), no launch_bounds min-blocks (regs<=32 spills, R12).
// ---------------------------------------------------------------------------
__global__ void __launch_bounds__(256) pool_kernel(const float4* __restrict__ feats,
                                                   float4* __restrict__ out) {
    int warp = (blockIdx.x * blockDim.x + threadIdx.x) >> 5;
    if (warp >= NUM_SEG) return;
    int lane = threadIdx.x & 31;

    int cnt = g_counts[warp];
    if (cnt > CAP) cnt = CAP;
    const int* __restrict__ lst = &g_bucket[warp * CAP];

    float4 acc = make_float4(-FLT_MAX, -FLT_MAX, -FLT_MAX, -FLT_MAX);

    int i = 0;
    for (; i + 4 <= cnt; i += 4) {
        int i0 = __ldg(lst + i + 0);
        int i1 = __ldg(lst + i + 1);
        int i2 = __ldg(lst + i + 2);
        int i3 = __ldg(lst + i + 3);
        float4 v0 = __ldg(&feats[(long)i0 * 32 + lane]);
        float4 v1 = __ldg(&feats[(long)i1 * 32 + lane]);
        float4 v2 = __ldg(&feats[(long)i2 * 32 + lane]);
        float4 v3 = __ldg(&feats[(long)i3 * 32 + lane]);
        acc.x = fmaxf(acc.x, fmaxf(fmaxf(v0.x, v1.x), fmaxf(v2.x, v3.x)));
        acc.y = fmaxf(acc.y, fmaxf(fmaxf(v0.y, v1.y), fmaxf(v2.y, v3.y)));
        acc.z = fmaxf(acc.z, fmaxf(fmaxf(v0.z, v1.z), fmaxf(v2.z, v3.z)));
        acc.w = fmaxf(acc.w, fmaxf(fmaxf(v0.w, v1.w), fmaxf(v2.w, v3.w)));
    }
    for (; i < cnt; i++) {
        int idx = __ldg(lst + i);
        float4 v = __ldg(&feats[(long)idx * 32 + lane]);
        acc.x = fmaxf(acc.x, v.x);
        acc.y = fmaxf(acc.y, v.y);
        acc.z = fmaxf(acc.z, v.z);
        acc.w = fmaxf(acc.w, v.w);
    }

    if (cnt == 0) acc = make_float4(0.f, 0.f, 0.f, 0.f);  // empty voxel -> zeros
    out[(long)warp * 32 + lane] = acc;
}

// ---------------------------------------------------------------------------
extern "C" void kernel_launch(void* const* d_in, const int* in_sizes, int n_in,
                              void* d_out, int out_size) {
    const float* feats  = (const float*)d_in[0];  // [N, 128] f32
    const int*   coords = (const int*)d_in[1];    // [N, 3]   i32
    float*       out    = (float*)d_out;          // [32768, 128] f32

    int n = in_sizes[1] / 3;  // N points

    zero_counts_kernel<<<32, 256>>>();                       // 8192 thr * int4
    scatter_kernel<<<(n + 255) / 256, 256>>>(coords, n);
    pool_kernel<<<NUM_SEG / 8, 256>>>((const float4*)feats, (float4*)out);
}

// round 15
// speedup vs baseline: 1.0205x; 1.0205x over previous
#include <cuda_runtime.h>
#include <float.h>

#define OUT_G    32
#define NUM_SEG  32768          // 32^3
#define CAP      128            // bucket capacity (Poisson mean ~30.5; >100 essentially impossible)

// Scratch (static __device__ — no allocation allowed)
__device__ int g_counts[NUM_SEG];            // per-segment count
__device__ int g_bucket[NUM_SEG * CAP];      // fixed-capacity point-index buckets (16 MB)

// ---------------------------------------------------------------------------
// Pass 1: zero the counts. Separate kernel is mandatory:
//   - fusing the reset into pool_kernel costs +60-80us (R8 vs R9 A/B)
//   - a graph memset node costs +5us vs this kernel (R11)
//   - vectorizing / shrinking the grid does not move it (pure launch latency)
// ---------------------------------------------------------------------------
__global__ void zero_counts_kernel() {
    int i = blockIdx.x * blockDim.x + threadIdx.x;
    if (i < NUM_SEG) g_counts[i] = 0;
}

// ---------------------------------------------------------------------------
// Pass 2: fused seg-id + scatter into fixed-capacity buckets.
// One point per thread — proven-fastest (2-pt neutral R10, 4-pt worse R3).
// ~18.5us: bound by scattered-atomic + scattered-store L1tex wavefronts.
// ---------------------------------------------------------------------------
__global__ void scatter_kernel(const int* __restrict__ coords, int n) {
    int i = blockIdx.x * blockDim.x + threadIdx.x;
    if (i >= n) return;
    int x = coords[3 * i + 0];
    int y = coords[3 * i + 1];
    int z = coords[3 * i + 2];
    int s = ((x >> 1) * OUT_G + (y >> 1)) * OUT_G + (z >> 1);
    int pos = atomicAdd(&g_counts[s], 1);
    if (pos < CAP) g_bucket[s * CAP + pos] = i;
}

// ---------------------------------------------------------------------------
// Pass 3: gather + max reduce. ONE WARP per output voxel (32 lanes x float4
// = 128 channels). Proven-optimal loop: 4 independent scalar index loads
// then 4 independent float4 gathers, branch-free body -> front-batched LDGs
// at ~5.9 TB/s (random-512B-gather DRAM ceiling). Block 256 (measured best).
// STRICTLY read-only except the final output store — no g_counts writes
// (measured toxic), no launch_bounds min-blocks (regs<=32 spills, R12).
// ---------------------------------------------------------------------------
__global__ void __launch_bounds__(256) pool_kernel(const float4* __restrict__ feats,
                                                   float4* __restrict__ out) {
    int warp = (blockIdx.x * blockDim.x + threadIdx.x) >> 5;
    if (warp >= NUM_SEG) return;
    int lane = threadIdx.x & 31;

    int cnt = g_counts[warp];
    if (cnt > CAP) cnt = CAP;
    const int* __restrict__ lst = &g_bucket[warp * CAP];

    float4 acc = make_float4(-FLT_MAX, -FLT_MAX, -FLT_MAX, -FLT_MAX);

    int i = 0;
    for (; i + 4 <= cnt; i += 4) {
        int i0 = __ldg(lst + i + 0);
        int i1 = __ldg(lst + i + 1);
        int i2 = __ldg(lst + i + 2);
        int i3 = __ldg(lst + i + 3);
        float4 v0 = __ldg(&feats[(long)i0 * 32 + lane]);
        float4 v1 = __ldg(&feats[(long)i1 * 32 + lane]);
        float4 v2 = __ldg(&feats[(long)i2 * 32 + lane]);
        float4 v3 = __ldg(&feats[(long)i3 * 32 + lane]);
        acc.x = fmaxf(acc.x, fmaxf(fmaxf(v0.x, v1.x), fmaxf(v2.x, v3.x)));
        acc.y = fmaxf(acc.y, fmaxf(fmaxf(v0.y, v1.y), fmaxf(v2.y, v3.y)));
        acc.z = fmaxf(acc.z, fmaxf(fmaxf(v0.z, v1.z), fmaxf(v2.z, v3.z)));
        acc.w = fmaxf(acc.w, fmaxf(fmaxf(v0.w, v1.w), fmaxf(v2.w, v3.w)));
    }
    for (; i < cnt; i++) {
        int idx = __ldg(lst + i);
        float4 v = __ldg(&feats[(long)idx * 32 + lane]);
        acc.x = fmaxf(acc.x, v.x);
        acc.y = fmaxf(acc.y, v.y);
        acc.z = fmaxf(acc.z, v.z);
        acc.w = fmaxf(acc.w, v.w);
    }

    if (cnt == 0) acc = make_float4(0.f, 0.f, 0.f, 0.f);  // empty voxel -> zeros
    out[(long)warp * 32 + lane] = acc;
}

// ---------------------------------------------------------------------------
extern "C" void kernel_launch(void* const* d_in, const int* in_sizes, int n_in,
                              void* d_out, int out_size) {
    const float* feats  = (const float*)d_in[0];  // [N, 128] f32
    const int*   coords = (const int*)d_in[1];    // [N, 3]   i32
    float*       out    = (float*)d_out;          // [32768, 128] f32

    int n = in_sizes[1] / 3;  // N points

    zero_counts_kernel<<<(NUM_SEG + 255) / 256, 256>>>();
    scatter_kernel<<<(n + 255) / 256, 256>>>(coords, n);
    pool_kernel<<<NUM_SEG / 8, 256>>>((const float4*)feats, (float4*)out);
}

// round 16
// speedup vs baseline: 1.0278x; 1.0071x over previous
#include <cuda_runtime.h>
#include <float.h>

#define OUT_G    32
#define NUM_SEG  32768          // 32^3
#define CAP      128            // bucket capacity (Poisson mean ~30.5; >100 essentially impossible)

// Scratch (static __device__ — no allocation allowed)
__device__ int g_counts[NUM_SEG];            // per-segment count
__device__ int g_bucket[NUM_SEG * CAP];      // fixed-capacity point-index buckets (16 MB)

// ---------------------------------------------------------------------------
// Pass 1: zero the counts. Separate kernel is mandatory:
//   - fusing the reset into pool_kernel costs +60-80us (R8 vs R9 A/B)
//   - a graph memset node costs +5us vs this kernel (R11)
//   - vectorizing / shrinking the grid does not move it (pure launch latency)
// ---------------------------------------------------------------------------
__global__ void zero_counts_kernel() {
    int i = blockIdx.x * blockDim.x + threadIdx.x;
    if (i < NUM_SEG) g_counts[i] = 0;
}

// ---------------------------------------------------------------------------
// Pass 2: fused seg-id + scatter into fixed-capacity buckets.
// One point per thread — proven-fastest (2-pt neutral R10, 4-pt worse R3).
// ~18.5us: bound by scattered-atomic + scattered-store L1tex wavefronts.
// ---------------------------------------------------------------------------
__global__ void scatter_kernel(const int* __restrict__ coords, int n) {
    int i = blockIdx.x * blockDim.x + threadIdx.x;
    if (i >= n) return;
    int x = coords[3 * i + 0];
    int y = coords[3 * i + 1];
    int z = coords[3 * i + 2];
    int s = ((x >> 1) * OUT_G + (y >> 1)) * OUT_G + (z >> 1);
    int pos = atomicAdd(&g_counts[s], 1);
    if (pos < CAP) g_bucket[s * CAP + pos] = i;
}

// ---------------------------------------------------------------------------
// Pass 3: gather + max reduce. ONE WARP per output voxel (32 lanes x float4
// = 128 channels). Proven-optimal loop: 4 independent scalar index loads
// then 4 independent float4 gathers, branch-free body -> front-batched LDGs
// at ~5.9 TB/s (random-512B-gather DRAM ceiling). Block 256 (measured best).
// STRICTLY read-only except the final output store — no g_counts writes
// (measured toxic), no launch_bounds min-blocks (regs<=32 spills, R12).
// ---------------------------------------------------------------------------
__global__ void __launch_bounds__(256) pool_kernel(const float4* __restrict__ feats,
                                                   float4* __restrict__ out) {
    int warp = (blockIdx.x * blockDim.x + threadIdx.x) >> 5;
    if (warp >= NUM_SEG) return;
    int lane = threadIdx.x & 31;

    int cnt = g_counts[warp];
    if (cnt > CAP) cnt = CAP;
    const int* __restrict__ lst = &g_bucket[warp * CAP];

    float4 acc = make_float4(-FLT_MAX, -FLT_MAX, -FLT_MAX, -FLT_MAX);

    int i = 0;
    for (; i + 4 <= cnt; i += 4) {
        int i0 = __ldg(lst + i + 0);
        int i1 = __ldg(lst + i + 1);
        int i2 = __ldg(lst + i + 2);
        int i3 = __ldg(lst + i + 3);
        float4 v0 = __ldg(&feats[(long)i0 * 32 + lane]);
        float4 v1 = __ldg(&feats[(long)i1 * 32 + lane]);
        float4 v2 = __ldg(&feats[(long)i2 * 32 + lane]);
        float4 v3 = __ldg(&feats[(long)i3 * 32 + lane]);
        acc.x = fmaxf(acc.x, fmaxf(fmaxf(v0.x, v1.x), fmaxf(v2.x, v3.x)));
        acc.y = fmaxf(acc.y, fmaxf(fmaxf(v0.y, v1.y), fmaxf(v2.y, v3.y)));
        acc.z = fmaxf(acc.z, fmaxf(fmaxf(v0.z, v1.z), fmaxf(v2.z, v3.z)));
        acc.w = fmaxf(acc.w, fmaxf(fmaxf(v0.w, v1.w), fmaxf(v2.w, v3.w)));
    }
    for (; i < cnt; i++) {
        int idx = __ldg(lst + i);
        float4 v = __ldg(&feats[(long)idx * 32 + lane]);
        acc.x = fmaxf(acc.x, v.x);
        acc.y = fmaxf(acc.y, v.y);
        acc.z = fmaxf(acc.z, v.z);
        acc.w = fmaxf(acc.w, v.w);
    }

    if (cnt == 0) acc = make_float4(0.f, 0.f, 0.f, 0.f);  // empty voxel -> zeros
    out[(long)warp * 32 + lane] = acc;
}

// ---------------------------------------------------------------------------
extern "C" void kernel_launch(void* const* d_in, const int* in_sizes, int n_in,
                              void* d_out, int out_size) {
    const float* feats  = (const float*)d_in[0];  // [N, 128] f32
    const int*   coords = (const int*)d_in[1];    // [N, 3]   i32
    float*       out    = (float*)d_out;          // [32768, 128] f32

    int n = in_sizes[1] / 3;  // N points

    zero_counts_kernel<<<(NUM_SEG + 255) / 256, 256>>>();
    scatter_kernel<<<(n + 255) / 256, 256>>>(coords, n);
    pool_kernel<<<NUM_SEG / 8, 256>>>((const float4*)feats, (float4*)out);
}

// round 17
// speedup vs baseline: 1.0933x; 1.0638x over previous
#include <cuda_runtime.h>
#include <float.h>

#define OUT_G    32
#define NUM_SEG  32768          // 32^3
#define CAP      128            // bucket capacity (Poisson mean ~30.5; >100 essentially impossible)

// Scratch (static __device__ — no allocation allowed)
__device__ int g_counts[NUM_SEG];            // per-segment count
__device__ int g_bucket[NUM_SEG * CAP];      // fixed-capacity point-index buckets (16 MB)

// ---------------------------------------------------------------------------
// Pass 1: zero the counts. Separate kernel is mandatory:
//   - fusing the reset into pool_kernel costs +60-80us (R8 vs R9 A/B)
//   - a graph memset node costs +5us vs this kernel (R11)
//   - vectorizing / shrinking the grid does not move it (pure launch latency)
// ---------------------------------------------------------------------------
__global__ void zero_counts_kernel() {
    int i = blockIdx.x * blockDim.x + threadIdx.x;
    if (i < NUM_SEG) g_counts[i] = 0;
}

// ---------------------------------------------------------------------------
// Pass 2: fused seg-id + scatter into fixed-capacity buckets.
// One point per thread — proven-fastest (2-pt neutral R10, 4-pt worse R3).
// ~18.5us: bound by scattered-atomic + scattered-store L1tex wavefronts.
// ---------------------------------------------------------------------------
__global__ void scatter_kernel(const int* __restrict__ coords, int n) {
    int i = blockIdx.x * blockDim.x + threadIdx.x;
    if (i >= n) return;
    int x = coords[3 * i + 0];
    int y = coords[3 * i + 1];
    int z = coords[3 * i + 2];
    int s = ((x >> 1) * OUT_G + (y >> 1)) * OUT_G + (z >> 1);
    int pos = atomicAdd(&g_counts[s], 1);
    if (pos < CAP) g_bucket[s * CAP + pos] = i;
}

// ---------------------------------------------------------------------------
// Pass 3: gather + max reduce. ONE WARP per output voxel (32 lanes x float4
// = 128 channels). Proven-optimal loop: 4 independent scalar index loads
// then 4 independent float4 gathers, branch-free body -> front-batched LDGs
// at ~5.9 TB/s. NEW (only delta vs the 108.3us best): feats gathers use
// __ldcs and the output store __stcs — streaming/evict-first policy, since
// every feats row is read exactly once (zero reuse; caching is pollution).
// Same instruction count/schedule, only the .CS modifier changes.
// STRICTLY read-only except the output store; no g_counts writes (toxic);
// no launch_bounds min-blocks (regs<=32 spills, R12).
// ---------------------------------------------------------------------------
__global__ void __launch_bounds__(256) pool_kernel(const float4* __restrict__ feats,
                                                   float4* __restrict__ out) {
    int warp = (blockIdx.x * blockDim.x + threadIdx.x) >> 5;
    if (warp >= NUM_SEG) return;
    int lane = threadIdx.x & 31;

    int cnt = g_counts[warp];
    if (cnt > CAP) cnt = CAP;
    const int* __restrict__ lst = &g_bucket[warp * CAP];

    float4 acc = make_float4(-FLT_MAX, -FLT_MAX, -FLT_MAX, -FLT_MAX);

    int i = 0;
    for (; i + 4 <= cnt; i += 4) {
        int i0 = __ldg(lst + i + 0);
        int i1 = __ldg(lst + i + 1);
        int i2 = __ldg(lst + i + 2);
        int i3 = __ldg(lst + i + 3);
        float4 v0 = __ldcs(&feats[(long)i0 * 32 + lane]);
        float4 v1 = __ldcs(&feats[(long)i1 * 32 + lane]);
        float4 v2 = __ldcs(&feats[(long)i2 * 32 + lane]);
        float4 v3 = __ldcs(&feats[(long)i3 * 32 + lane]);
        acc.x = fmaxf(acc.x, fmaxf(fmaxf(v0.x, v1.x), fmaxf(v2.x, v3.x)));
        acc.y = fmaxf(acc.y, fmaxf(fmaxf(v0.y, v1.y), fmaxf(v2.y, v3.y)));
        acc.z = fmaxf(acc.z, fmaxf(fmaxf(v0.z, v1.z), fmaxf(v2.z, v3.z)));
        acc.w = fmaxf(acc.w, fmaxf(fmaxf(v0.w, v1.w), fmaxf(v2.w, v3.w)));
    }
    for (; i < cnt; i++) {
        int idx = __ldg(lst + i);
        float4 v = __ldcs(&feats[(long)idx * 32 + lane]);
        acc.x = fmaxf(acc.x, v.x);
        acc.y = fmaxf(acc.y, v.y);
        acc.z = fmaxf(acc.z, v.z);
        acc.w = fmaxf(acc.w, v.w);
    }

    if (cnt == 0) acc = make_float4(0.f, 0.f, 0.f, 0.f);  // empty voxel -> zeros
    __stcs(&out[(long)warp * 32 + lane], acc);
}

// ---------------------------------------------------------------------------
extern "C" void kernel_launch(void* const* d_in, const int* in_sizes, int n_in,
                              void* d_out, int out_size) {
    const float* feats  = (const float*)d_in[0];  // [N, 128] f32
    const int*   coords = (const int*)d_in[1];    // [N, 3]   i32
    float*       out    = (float*)d_out;          // [32768, 128] f32

    int n = in_sizes[1] / 3;  // N points

    zero_counts_kernel<<<(NUM_SEG + 255) / 256, 256>>>();
    scatter_kernel<<<(n + 255) / 256, 256>>>(coords, n);
    pool_kernel<<<NUM_SEG / 8, 256>>>((const float4*)feats, (float4*)out);
}